// round 3
// baseline (speedup 1.0000x reference)
#include <cuda_runtime.h>
#include <cstdint>
#include <cstddef>

#define B_   2048
#define E_   512
#define EMB_ 256
#define AR_  1024
#define H256_ 256
#define H32_  32
#define NT_   256

// Scratch (no cudaMalloc allowed)
__device__ float g_T[B_ * H256_];    // relu(mask@W_func + b_func)
__device__ float g_W12[AR_ * H32_];  // W_fc1 @ W_fc2
__device__ float g_bvec[H32_];       // b_fc1 @ W_fc2 + b_fc2
__device__ float g_w[B_ * EMB_];     // W_conv @ query[b]
__device__ float g_c0[B_];           // b_conv . query[b]

// ---------------------------------------------------------------------------
// Threefry2x32-20, JAX partitionable variant: counter (hi=0, lo=index),
// output = out0 ^ out1, key = (0, 42).
// ---------------------------------------------------------------------------
__device__ __forceinline__ uint32_t rotl32(uint32_t x, int r) {
    return (x << r) | (x >> (32 - r));
}

__device__ __forceinline__ uint32_t threefry_bits(uint32_t k0, uint32_t k1,
                                                  uint32_t c0, uint32_t c1) {
    uint32_t ks2 = k0 ^ k1 ^ 0x1BD11BDAu;
    uint32_t x0 = c0 + k0;
    uint32_t x1 = c1 + k1;
#define TF_RND(r) { x0 += x1; x1 = rotl32(x1, (r)); x1 ^= x0; }
    TF_RND(13) TF_RND(15) TF_RND(26) TF_RND(6)
    x0 += k1;  x1 += ks2 + 1u;
    TF_RND(17) TF_RND(29) TF_RND(16) TF_RND(24)
    x0 += ks2; x1 += k0 + 2u;
    TF_RND(13) TF_RND(15) TF_RND(26) TF_RND(6)
    x0 += k0;  x1 += k1 + 3u;
    TF_RND(17) TF_RND(29) TF_RND(16) TF_RND(24)
    x0 += k1;  x1 += ks2 + 4u;
    TF_RND(13) TF_RND(15) TF_RND(26) TF_RND(6)
    x0 += ks2; x1 += k0 + 5u;
#undef TF_RND
    return x0 ^ x1;
}

__device__ __forceinline__ float gumbel_from_index(uint32_t idx) {
    uint32_t bits = threefry_bits(0u, 42u, 0u, idx);
    float u = __uint_as_float((bits >> 9) | 0x3f800000u) - 1.0f;
    const float tiny = 1.17549435e-38f;
    u = fmaxf(tiny, u + tiny);
    return -logf(-logf(u));
}

// ---------------------------------------------------------------------------
// P0: g_W12 = W_fc1 @ W_fc2 (1024x32), g_bvec = b_fc1 @ W_fc2 + b_fc2.
// ---------------------------------------------------------------------------
__global__ __launch_bounds__(256)
void kernelP0(const float* __restrict__ W_fc1, const float* __restrict__ W_fc2,
              const float* __restrict__ b_fc1, const float* __restrict__ b_fc2) {
    __shared__ float s_w2[H256_ * H32_];   // 32KB
    const int tid = threadIdx.x;
    const int warp = tid >> 5, lane = tid & 31;
    for (int i = tid; i < H256_ * H32_; i += 256) s_w2[i] = W_fc2[i];
    __syncthreads();

    const int r = blockIdx.x * 8 + warp;
    const float* frow = W_fc1 + r * H256_;
    float a0 = 0.f, a1 = 0.f, a2 = 0.f, a3 = 0.f;
#pragma unroll 8
    for (int k0 = 0; k0 < H256_; k0 += 4) {
        float4 f = *(const float4*)(frow + k0);
        a0 += f.x * s_w2[(k0 + 0) * H32_ + lane];
        a1 += f.y * s_w2[(k0 + 1) * H32_ + lane];
        a2 += f.z * s_w2[(k0 + 2) * H32_ + lane];
        a3 += f.w * s_w2[(k0 + 3) * H32_ + lane];
    }
    g_W12[r * H32_ + lane] = (a0 + a1) + (a2 + a3);

    if (blockIdx.x == 0 && warp == 0) {
        float b0 = b_fc2[lane];
#pragma unroll 8
        for (int k = 0; k < H256_; k++) b0 += b_fc1[k] * s_w2[k * H32_ + lane];
        g_bvec[lane] = b0;
    }
}

// ---------------------------------------------------------------------------
// Q1: g_T = relu(maskf @ W_func + b_func).
// BM=32, BN=64, BK=32, 256 threads, 2x4 micro-tile, grid (64,4)=256 blocks.
// ---------------------------------------------------------------------------
__global__ __launch_bounds__(256)
void kernelQ1(const int* __restrict__ utm, const float* __restrict__ W_func,
              const float* __restrict__ b_func) {
    __shared__ float As[32][33];   // [k][m], padded
    __shared__ float Bs[32][64];   // [k][n]

    const int bm = blockIdx.x * 32;
    const int bn = blockIdx.y * 64;
    const int tid = threadIdx.x;
    const int tx = tid & 15;       // n group: cols tx*4..+3
    const int ty = tid >> 4;       // m group: rows ty*2..+1

    const int lAr = tid >> 3;            // 0..31 row
    const int lAk = (tid & 7) * 4;       // k offset 0..28

    float acc[2][4];
#pragma unroll
    for (int i = 0; i < 2; i++)
#pragma unroll
        for (int j = 0; j < 4; j++) acc[i][j] = 0.0f;

    for (int k0 = 0; k0 < NT_; k0 += 32) {
        int4 mi = *(const int4*)(utm + (bm + lAr) * NT_ + k0 + lAk);
        As[lAk + 0][lAr] = (float)mi.x;
        As[lAk + 1][lAr] = (float)mi.y;
        As[lAk + 2][lAr] = (float)mi.z;
        As[lAk + 3][lAr] = (float)mi.w;
#pragma unroll
        for (int i = 0; i < 2; i++) {
            int f = tid + i * 256;           // 0..511
            int kr = f >> 4, c = (f & 15) * 4;
            *(float4*)&Bs[kr][c] = *(const float4*)(W_func + (k0 + kr) * H256_ + bn + c);
        }
        __syncthreads();
#pragma unroll
        for (int kk = 0; kk < 32; kk++) {
            float a0 = As[kk][ty * 2];
            float a1 = As[kk][ty * 2 + 1];
            float4 b4 = *(const float4*)&Bs[kk][tx * 4];
            acc[0][0] += a0 * b4.x; acc[0][1] += a0 * b4.y;
            acc[0][2] += a0 * b4.z; acc[0][3] += a0 * b4.w;
            acc[1][0] += a1 * b4.x; acc[1][1] += a1 * b4.y;
            acc[1][2] += a1 * b4.z; acc[1][3] += a1 * b4.w;
        }
        __syncthreads();
    }

#pragma unroll
    for (int i = 0; i < 2; i++) {
        const int row = bm + ty * 2 + i;
#pragma unroll
        for (int j = 0; j < 4; j++) {
            const int col = bn + tx * 4 + j;
            g_T[row * H256_ + col] = fmaxf(acc[i][j] + b_func[col], 0.0f);
        }
    }
}

// ---------------------------------------------------------------------------
// Z: fused z2 + LSTM + w + c0. Block = 256 threads = 8 warps, 2 b's per block
// (4 warps per b, each a K-quarter of the combined 1280-reduction).
// grid = 1024.
// ---------------------------------------------------------------------------
__global__ __launch_bounds__(256)
void kernelZ(const float* __restrict__ ar, const float* __restrict__ W_fc2,
             const float* __restrict__ lk, const float* __restrict__ lb,
             const float* __restrict__ W_conv, const float* __restrict__ b_conv) {
    const int warp = threadIdx.x >> 5;
    const int lane = threadIdx.x & 31;
    const int sub = warp >> 2;     // which b in block (0/1)
    const int wq  = warp & 3;      // k-quarter
    const int b = blockIdx.x * 2 + sub;

    __shared__ float zpart[2][4][32];
    __shared__ float qs[2][32];

    // ---- phase 1: partial z2 ----
    float acc = 0.0f;
    const float* Trow = g_T + b * H256_;
#pragma unroll 4
    for (int k0 = wq * 64; k0 < wq * 64 + 64; k0 += 4) {
        float4 t = *(const float4*)(Trow + k0);                 // uniform bcast
        acc += t.x * W_fc2[(k0 + 0) * H32_ + lane];
        acc += t.y * W_fc2[(k0 + 1) * H32_ + lane];
        acc += t.z * W_fc2[(k0 + 2) * H32_ + lane];
        acc += t.w * W_fc2[(k0 + 3) * H32_ + lane];
    }
    const float* arow = ar + (size_t)b * AR_;
#pragma unroll 8
    for (int k0 = wq * 256; k0 < wq * 256 + 256; k0 += 4) {
        float4 a = *(const float4*)(arow + k0);                 // uniform bcast
        acc += a.x * g_W12[(k0 + 0) * H32_ + lane];
        acc += a.y * g_W12[(k0 + 1) * H32_ + lane];
        acc += a.z * g_W12[(k0 + 2) * H32_ + lane];
        acc += a.w * g_W12[(k0 + 3) * H32_ + lane];
    }
    zpart[sub][wq][lane] = acc;
    __syncthreads();

    // ---- phase 2: combine + LSTM (warps 0 and 4) ----
    if (wq == 0) {
        float z = g_bvec[lane]
                + (zpart[sub][0][lane] + zpart[sub][1][lane])
                + (zpart[sub][2][lane] + zpart[sub][3][lane]);
        zpart[sub][0][lane] = z;
        __syncwarp();
        float zi = lb[lane];
        float zg = lb[64 + lane];
        float zo = lb[96 + lane];
#pragma unroll
        for (int m = 0; m < 32; m++) {
            float v = zpart[sub][0][m];
            zi += v * lk[m * 128 + lane];
            zg += v * lk[m * 128 + 64 + lane];
            zo += v * lk[m * 128 + 96 + lane];
        }
        float ig = 1.0f / (1.0f + expf(-zi));
        float gg = tanhf(zg);
        float og = 1.0f / (1.0f + expf(-zo));
        float c  = ig * gg;
        float h  = og * tanhf(c);
        qs[sub][lane] = h;
        // c0 = b_conv . query
        float part = b_conv[lane] * h;
#pragma unroll
        for (int s = 16; s > 0; s >>= 1) part += __shfl_xor_sync(0xffffffffu, part, s);
        if (lane == 0) g_c0[b] = part;
    }
    __syncthreads();

    // ---- phase 3: w[d] = W_conv[d,:] . q, each warp covers 64 d's ----
#pragma unroll
    for (int dd = 0; dd < 2; dd++) {
        const int d = wq * 64 + dd * 32 + lane;
        const float* wr = W_conv + d * H32_;
        float s0 = 0.f, s1 = 0.f;
#pragma unroll
        for (int m = 0; m < 32; m += 4) {
            float4 wc = *(const float4*)(wr + m);
            s0 += wc.x * qs[sub][m + 0] + wc.y * qs[sub][m + 1];
            s1 += wc.z * qs[sub][m + 2] + wc.w * qs[sub][m + 3];
        }
        g_w[b * EMB_ + d] = s0 + s1;
    }
}

// ---------------------------------------------------------------------------
// Kernel B: per-b block. y[e] = ee[b,e,:].w[b] + c0[b]; masked logit stores
// immediately; shuffle-based softmax + gumbel argmax (4 barriers total).
// ---------------------------------------------------------------------------
__global__ __launch_bounds__(256)
void kernelB(const float* __restrict__ ee, const int* __restrict__ tum,
             float* __restrict__ out, int mode) {
    const int b = blockIdx.x;
    const int tid = threadIdx.x;
    const int warp = tid >> 5;
    const int lane = tid & 31;

    __shared__ float ys[512];
    __shared__ float wred[8];
    __shared__ float wred2[8];
    __shared__ float wv[8];
    __shared__ int   wi[8];

    const float* wb = g_w + b * EMB_;
    const float4 w0 = *(const float4*)(wb + 4 * lane);
    const float4 w1 = *(const float4*)(wb + 128 + 4 * lane);
    const float cb = g_c0[b];
    const int tm = tum[b];
    const float4* eb = (const float4*)(ee + (size_t)b * E_ * EMB_);

#pragma unroll
    for (int it = 0; it < 16; it++) {
        const int e0 = it * 32 + warp * 4;
        float4 r0a = __ldcs(eb + (size_t)(e0 + 0) * 64 + lane);
        float4 r0b = __ldcs(eb + (size_t)(e0 + 0) * 64 + 32 + lane);
        float4 r1a = __ldcs(eb + (size_t)(e0 + 1) * 64 + lane);
        float4 r1b = __ldcs(eb + (size_t)(e0 + 1) * 64 + 32 + lane);
        float4 r2a = __ldcs(eb + (size_t)(e0 + 2) * 64 + lane);
        float4 r2b = __ldcs(eb + (size_t)(e0 + 2) * 64 + 32 + lane);
        float4 r3a = __ldcs(eb + (size_t)(e0 + 3) * 64 + lane);
        float4 r3b = __ldcs(eb + (size_t)(e0 + 3) * 64 + 32 + lane);

        float s0 = r0a.x * w0.x + r0a.y * w0.y + r0a.z * w0.z + r0a.w * w0.w
                 + r0b.x * w1.x + r0b.y * w1.y + r0b.z * w1.z + r0b.w * w1.w;
        float s1 = r1a.x * w0.x + r1a.y * w0.y + r1a.z * w0.z + r1a.w * w0.w
                 + r1b.x * w1.x + r1b.y * w1.y + r1b.z * w1.z + r1b.w * w1.w;
        float s2 = r2a.x * w0.x + r2a.y * w0.y + r2a.z * w0.z + r2a.w * w0.w
                 + r2b.x * w1.x + r2b.y * w1.y + r2b.z * w1.z + r2b.w * w1.w;
        float s3 = r3a.x * w0.x + r3a.y * w0.y + r3a.z * w0.z + r3a.w * w0.w
                 + r3b.x * w1.x + r3b.y * w1.y + r3b.z * w1.z + r3b.w * w1.w;
#pragma unroll
        for (int o = 16; o > 0; o >>= 1) {
            s0 += __shfl_xor_sync(0xffffffffu, s0, o);
            s1 += __shfl_xor_sync(0xffffffffu, s1, o);
            s2 += __shfl_xor_sync(0xffffffffu, s2, o);
            s3 += __shfl_xor_sync(0xffffffffu, s3, o);
        }
        if (lane == 0) {
            ys[e0 + 0] = s0 + cb;
            ys[e0 + 1] = s1 + cb;
            ys[e0 + 2] = s2 + cb;
            ys[e0 + 3] = s3 + cb;
        }
    }
    __syncthreads();   // barrier 1

    const float y0 = ys[tid];
    const float y1 = ys[tid + 256];

    // masked logit stores: fire-and-forget, overlap with reductions
    const float mf = (float)tm;
    out[(size_t)b * 512 + tid]       = y0 * mf;
    out[(size_t)b * 512 + tid + 256] = y1 * mf;

    // gumbel noise (pure ALU, independent of reductions)
    const float gb0 = gumbel_from_index((uint32_t)(b * 512 + tid));
    const float gb1 = gumbel_from_index((uint32_t)(b * 512 + tid + 256));

    // ---- max ----
    float m = fmaxf(y0, y1);
#pragma unroll
    for (int o = 16; o > 0; o >>= 1) m = fmaxf(m, __shfl_xor_sync(0xffffffffu, m, o));
    if (lane == 0) wred[warp] = m;
    __syncthreads();   // barrier 2
    float maxv = wred[0];
#pragma unroll
    for (int i = 1; i < 8; i++) maxv = fmaxf(maxv, wred[i]);

    // ---- exp + sum ----
    const float e0v = expf(y0 - maxv);
    const float e1v = expf(y1 - maxv);
    float s = e0v + e1v;
#pragma unroll
    for (int o = 16; o > 0; o >>= 1) s += __shfl_xor_sync(0xffffffffu, s, o);
    if (lane == 0) wred2[warp] = s;
    __syncthreads();   // barrier 3
    float sumv = wred2[0];
#pragma unroll
    for (int i = 1; i < 8; i++) sumv += wred2[i];

    if (mode != 0) {
        // ---- probs + gumbel argmax (first-index tie-break) ----
        const float sc0 = e0v / sumv + gb0;
        const float sc1 = e1v / sumv + gb1;
        float bv; int bi;
        if (sc1 > sc0) { bv = sc1; bi = tid + 256; } else { bv = sc0; bi = tid; }
#pragma unroll
        for (int o = 16; o > 0; o >>= 1) {
            float ov = __shfl_xor_sync(0xffffffffu, bv, o);
            int   oi = __shfl_xor_sync(0xffffffffu, bi, o);
            if (ov > bv || (ov == bv && oi < bi)) { bv = ov; bi = oi; }
        }
        if (lane == 0) { wv[warp] = bv; wi[warp] = bi; }
        __syncthreads();   // barrier 4
        if (tid == 0) {
            float fv = wv[0]; int fi = wi[0];
#pragma unroll
            for (int i = 1; i < 8; i++) {
                if (wv[i] > fv || (wv[i] == fv && wi[i] < fi)) { fv = wv[i]; fi = wi[i]; }
            }
            long long id = (long long)fi * (long long)tm;
            if (mode == 1) out[1048576 + b] = (float)id;
            else ((long long*)(out + 1048576))[b] = id;
        }
    }
}

// ---------------------------------------------------------------------------
extern "C" void kernel_launch(void* const* d_in, const int* in_sizes, int n_in,
                              void* d_out, int out_size) {
    const float* ar     = (const float*)d_in[0];
    const int*   utm    = (const int*)d_in[1];
    const int*   tum    = (const int*)d_in[2];
    const float* ee     = (const float*)d_in[3];
    const float* W_func = (const float*)d_in[4];
    const float* b_func = (const float*)d_in[5];
    const float* W_conv = (const float*)d_in[6];
    const float* b_conv = (const float*)d_in[7];
    const float* W_fc1  = (const float*)d_in[8];
    const float* b_fc1  = (const float*)d_in[9];
    const float* W_fc2  = (const float*)d_in[10];
    const float* b_fc2  = (const float*)d_in[11];
    const float* lk     = (const float*)d_in[12];
    // d_in[13] = lstm_recurrent: unused (h0 = 0)
    const float* lb     = (const float*)d_in[14];

    kernelP0<<<128, 256>>>(W_fc1, W_fc2, b_fc1, b_fc2);
    kernelQ1<<<dim3(64, 4), 256>>>(utm, W_func, b_func);
    kernelZ<<<1024, 256>>>(ar, W_fc2, lk, lb, W_conv, b_conv);

    int mode = 0;
    if (out_size >= 1048576 + 4096)      mode = 2;
    else if (out_size >= 1048576 + 2048) mode = 1;
    kernelB<<<2048, 256>>>(ee, tum, (float*)d_out, mode);
}

// round 4
// speedup vs baseline: 1.0991x; 1.0991x over previous
#include <cuda_runtime.h>
#include <cstdint>
#include <cstddef>

#define B_   2048
#define E_   512
#define EMB_ 256
#define AR_  1024
#define H256_ 256
#define H32_  32
#define NT_   256

// Scratch (no cudaMalloc allowed)
__device__ float g_W12[AR_ * H32_];  // W_fc1 @ W_fc2
__device__ float g_bvec[H32_];       // b_fc1 @ W_fc2 + b_fc2

// ---------------------------------------------------------------------------
// Threefry2x32-20, JAX partitionable variant: counter (hi=0, lo=index),
// output = out0 ^ out1, key = (0, 42).
// ---------------------------------------------------------------------------
__device__ __forceinline__ uint32_t rotl32(uint32_t x, int r) {
    return (x << r) | (x >> (32 - r));
}

__device__ __forceinline__ uint32_t threefry_bits(uint32_t k0, uint32_t k1,
                                                  uint32_t c0, uint32_t c1) {
    uint32_t ks2 = k0 ^ k1 ^ 0x1BD11BDAu;
    uint32_t x0 = c0 + k0;
    uint32_t x1 = c1 + k1;
#define TF_RND(r) { x0 += x1; x1 = rotl32(x1, (r)); x1 ^= x0; }
    TF_RND(13) TF_RND(15) TF_RND(26) TF_RND(6)
    x0 += k1;  x1 += ks2 + 1u;
    TF_RND(17) TF_RND(29) TF_RND(16) TF_RND(24)
    x0 += ks2; x1 += k0 + 2u;
    TF_RND(13) TF_RND(15) TF_RND(26) TF_RND(6)
    x0 += k0;  x1 += k1 + 3u;
    TF_RND(17) TF_RND(29) TF_RND(16) TF_RND(24)
    x0 += k1;  x1 += ks2 + 4u;
    TF_RND(13) TF_RND(15) TF_RND(26) TF_RND(6)
    x0 += ks2; x1 += k0 + 5u;
#undef TF_RND
    return x0 ^ x1;
}

__device__ __forceinline__ float gumbel_from_index(uint32_t idx) {
    uint32_t bits = threefry_bits(0u, 42u, 0u, idx);
    float u = __uint_as_float((bits >> 9) | 0x3f800000u) - 1.0f;
    const float tiny = 1.17549435e-38f;
    u = fmaxf(tiny, u + tiny);
    return -logf(-logf(u));
}

// ---------------------------------------------------------------------------
// P0: g_W12 = W_fc1 @ W_fc2 (1024x32), g_bvec = b_fc1 @ W_fc2 + b_fc2.
// ---------------------------------------------------------------------------
__global__ __launch_bounds__(256)
void kernelP0(const float* __restrict__ W_fc1, const float* __restrict__ W_fc2,
              const float* __restrict__ b_fc1, const float* __restrict__ b_fc2) {
    __shared__ float s_w2[H256_ * H32_];   // 32KB
    const int tid = threadIdx.x;
    const int warp = tid >> 5, lane = tid & 31;
    for (int i = tid; i < H256_ * H32_; i += 256) s_w2[i] = W_fc2[i];
    __syncthreads();

    const int r = blockIdx.x * 8 + warp;
    const float* frow = W_fc1 + r * H256_;
    float a0 = 0.f, a1 = 0.f, a2 = 0.f, a3 = 0.f;
#pragma unroll 8
    for (int k0 = 0; k0 < H256_; k0 += 4) {
        float4 f = *(const float4*)(frow + k0);
        a0 += f.x * s_w2[(k0 + 0) * H32_ + lane];
        a1 += f.y * s_w2[(k0 + 1) * H32_ + lane];
        a2 += f.z * s_w2[(k0 + 2) * H32_ + lane];
        a3 += f.w * s_w2[(k0 + 3) * H32_ + lane];
    }
    g_W12[r * H32_ + lane] = (a0 + a1) + (a2 + a3);

    if (blockIdx.x == 0 && warp == 0) {
        float b0 = b_fc2[lane];
#pragma unroll 8
        for (int k = 0; k < H256_; k++) b0 += b_fc1[k] * s_w2[k * H32_ + lane];
        g_bvec[lane] = b0;
    }
}

// ---------------------------------------------------------------------------
// kernelBF: fully fused per-b block.
// Phase A: mask compaction -> t (active W_func row sum) -> z2 (8-warp split)
//          -> LSTM -> q -> w = W_conv@q, c0 = b_conv.q   (all smem-resident)
// Phase B: y[e] = ee[b,e,:].w + c0; masked logit stores; softmax; probs+gumbel
//          argmax; id store.
// ---------------------------------------------------------------------------
__global__ __launch_bounds__(256)
void kernelBF(const float* __restrict__ ar, const int* __restrict__ utm,
              const int* __restrict__ tum, const float* __restrict__ ee,
              const float* __restrict__ W_func, const float* __restrict__ b_func,
              const float* __restrict__ W_conv, const float* __restrict__ b_conv,
              const float* __restrict__ W_fc2,
              const float* __restrict__ lk, const float* __restrict__ lb,
              float* __restrict__ out, int mode) {
    const int b = blockIdx.x;
    const int tid = threadIdx.x;
    const int warp = tid >> 5;
    const int lane = tid & 31;

    __shared__ int   s_act[NT_];
    __shared__ int   s_wcnt[8];
    __shared__ float s_z2[8][32];
    __shared__ float s_q[32];
    __shared__ float s_w[EMB_];
    __shared__ float s_c0;
    __shared__ float ys[512];
    __shared__ float wred[8];
    __shared__ float wred2[8];
    __shared__ float wv[8];
    __shared__ int   wi[8];

    // ---- A1: deterministic mask compaction (ascending k order) ----
    const int mk = utm[b * NT_ + tid];
    const unsigned bal = __ballot_sync(0xffffffffu, mk != 0);
    if (lane == 0) s_wcnt[warp] = __popc(bal);
    __syncthreads();
    int base = 0;
#pragma unroll
    for (int i = 0; i < 8; i++) base += (i < warp) ? s_wcnt[i] : 0;
    if (mk) s_act[base + __popc(bal & ((1u << lane) - 1u))] = tid;
    __syncthreads();
    int nact = 0;
#pragma unroll
    for (int i = 0; i < 8; i++) nact += s_wcnt[i];

    // ---- A2: t_j = relu(b_func[j] + sum_{active k} W_func[k,j]), j = tid ----
    float t0 = 0.f, t1 = 0.f, t2 = 0.f, t3 = 0.f;
    int i = 0;
    for (; i + 4 <= nact; i += 4) {
        t0 += W_func[s_act[i + 0] * H256_ + tid];
        t1 += W_func[s_act[i + 1] * H256_ + tid];
        t2 += W_func[s_act[i + 2] * H256_ + tid];
        t3 += W_func[s_act[i + 3] * H256_ + tid];
    }
    for (; i < nact; i++) t0 += W_func[s_act[i] * H256_ + tid];
    const float tj = fmaxf(b_func[tid] + (t0 + t1) + (t2 + t3), 0.0f);

    // ---- A3: per-warp z2 partial: fold 32 t's + 128 ar terms ----
    float pz = 0.f;
#pragma unroll
    for (int jj = 0; jj < 32; jj++) {
        float tv = __shfl_sync(0xffffffffu, tj, jj);
        pz += tv * W_fc2[(warp * 32 + jj) * H32_ + lane];
    }
    const float* arow = ar + (size_t)b * AR_ + warp * 128;
    const float* w12p = g_W12 + (warp * 128) * H32_;
    float pa0 = 0.f, pa1 = 0.f, pa2 = 0.f, pa3 = 0.f;
#pragma unroll 2
    for (int r0 = 0; r0 < 128; r0 += 4) {
        float4 a = *(const float4*)(arow + r0);
        pa0 += a.x * w12p[(r0 + 0) * H32_ + lane];
        pa1 += a.y * w12p[(r0 + 1) * H32_ + lane];
        pa2 += a.z * w12p[(r0 + 2) * H32_ + lane];
        pa3 += a.w * w12p[(r0 + 3) * H32_ + lane];
    }
    s_z2[warp][lane] = pz + (pa0 + pa1) + (pa2 + pa3);
    __syncthreads();

    // ---- A4: warp 0: combine + LSTM (h0 = c0 = 0; f gate unused) ----
    if (warp == 0) {
        float z = g_bvec[lane];
#pragma unroll
        for (int w2 = 0; w2 < 8; w2++) z += s_z2[w2][lane];
        float zi = lb[lane];
        float zg = lb[64 + lane];
        float zo = lb[96 + lane];
#pragma unroll
        for (int m = 0; m < 32; m++) {
            float v = __shfl_sync(0xffffffffu, z, m);
            zi += v * lk[m * 128 + lane];
            zg += v * lk[m * 128 + 64 + lane];
            zo += v * lk[m * 128 + 96 + lane];
        }
        float ig = 1.0f / (1.0f + expf(-zi));
        float gg = tanhf(zg);
        float og = 1.0f / (1.0f + expf(-zo));
        float c  = ig * gg;
        float h  = og * tanhf(c);
        s_q[lane] = h;
        float part = b_conv[lane] * h;
#pragma unroll
        for (int s = 16; s > 0; s >>= 1) part += __shfl_xor_sync(0xffffffffu, part, s);
        if (lane == 0) s_c0 = part;
    }
    __syncthreads();

    // ---- A5: w[d] = W_conv[d,:] . q, d = tid ----
    {
        const float* wr = W_conv + tid * H32_;
        float s0 = 0.f, s1 = 0.f;
#pragma unroll
        for (int m = 0; m < 32; m += 4) {
            float4 wc = *(const float4*)(wr + m);
            s0 += wc.x * s_q[m + 0] + wc.y * s_q[m + 1];
            s1 += wc.z * s_q[m + 2] + wc.w * s_q[m + 3];
        }
        s_w[tid] = s0 + s1;
    }
    __syncthreads();

    // =========================== Phase B ===========================
    const float4 w0 = *(const float4*)(s_w + 4 * lane);
    const float4 w1 = *(const float4*)(s_w + 128 + 4 * lane);
    const float cb = s_c0;
    const int tm = tum[b];
    const float4* eb = (const float4*)(ee + (size_t)b * E_ * EMB_);

#pragma unroll
    for (int it = 0; it < 16; it++) {
        const int e0 = it * 32 + warp * 4;
        float4 r0a = __ldcs(eb + (size_t)(e0 + 0) * 64 + lane);
        float4 r0b = __ldcs(eb + (size_t)(e0 + 0) * 64 + 32 + lane);
        float4 r1a = __ldcs(eb + (size_t)(e0 + 1) * 64 + lane);
        float4 r1b = __ldcs(eb + (size_t)(e0 + 1) * 64 + 32 + lane);
        float4 r2a = __ldcs(eb + (size_t)(e0 + 2) * 64 + lane);
        float4 r2b = __ldcs(eb + (size_t)(e0 + 2) * 64 + 32 + lane);
        float4 r3a = __ldcs(eb + (size_t)(e0 + 3) * 64 + lane);
        float4 r3b = __ldcs(eb + (size_t)(e0 + 3) * 64 + 32 + lane);

        float s0 = r0a.x * w0.x + r0a.y * w0.y + r0a.z * w0.z + r0a.w * w0.w
                 + r0b.x * w1.x + r0b.y * w1.y + r0b.z * w1.z + r0b.w * w1.w;
        float s1 = r1a.x * w0.x + r1a.y * w0.y + r1a.z * w0.z + r1a.w * w0.w
                 + r1b.x * w1.x + r1b.y * w1.y + r1b.z * w1.z + r1b.w * w1.w;
        float s2 = r2a.x * w0.x + r2a.y * w0.y + r2a.z * w0.z + r2a.w * w0.w
                 + r2b.x * w1.x + r2b.y * w1.y + r2b.z * w1.z + r2b.w * w1.w;
        float s3 = r3a.x * w0.x + r3a.y * w0.y + r3a.z * w0.z + r3a.w * w0.w
                 + r3b.x * w1.x + r3b.y * w1.y + r3b.z * w1.z + r3b.w * w1.w;
#pragma unroll
        for (int o = 16; o > 0; o >>= 1) {
            s0 += __shfl_xor_sync(0xffffffffu, s0, o);
            s1 += __shfl_xor_sync(0xffffffffu, s1, o);
            s2 += __shfl_xor_sync(0xffffffffu, s2, o);
            s3 += __shfl_xor_sync(0xffffffffu, s3, o);
        }
        if (lane == 0) {
            ys[e0 + 0] = s0 + cb;
            ys[e0 + 1] = s1 + cb;
            ys[e0 + 2] = s2 + cb;
            ys[e0 + 3] = s3 + cb;
        }
    }
    __syncthreads();

    const float y0 = ys[tid];
    const float y1 = ys[tid + 256];

    // masked logit stores: fire-and-forget, overlap with reductions
    const float mf = (float)tm;
    out[(size_t)b * 512 + tid]       = y0 * mf;
    out[(size_t)b * 512 + tid + 256] = y1 * mf;

    // gumbel noise (pure ALU, independent of reductions)
    const float gb0 = gumbel_from_index((uint32_t)(b * 512 + tid));
    const float gb1 = gumbel_from_index((uint32_t)(b * 512 + tid + 256));

    // ---- max ----
    float m = fmaxf(y0, y1);
#pragma unroll
    for (int o = 16; o > 0; o >>= 1) m = fmaxf(m, __shfl_xor_sync(0xffffffffu, m, o));
    if (lane == 0) wred[warp] = m;
    __syncthreads();
    float maxv = wred[0];
#pragma unroll
    for (int i2 = 1; i2 < 8; i2++) maxv = fmaxf(maxv, wred[i2]);

    // ---- exp + sum ----
    const float e0v = expf(y0 - maxv);
    const float e1v = expf(y1 - maxv);
    float s = e0v + e1v;
#pragma unroll
    for (int o = 16; o > 0; o >>= 1) s += __shfl_xor_sync(0xffffffffu, s, o);
    if (lane == 0) wred2[warp] = s;
    __syncthreads();
    float sumv = wred2[0];
#pragma unroll
    for (int i2 = 1; i2 < 8; i2++) sumv += wred2[i2];

    if (mode != 0) {
        // ---- probs + gumbel argmax (first-index tie-break) ----
        const float sc0 = e0v / sumv + gb0;
        const float sc1 = e1v / sumv + gb1;
        float bv; int bi;
        if (sc1 > sc0) { bv = sc1; bi = tid + 256; } else { bv = sc0; bi = tid; }
#pragma unroll
        for (int o = 16; o > 0; o >>= 1) {
            float ov = __shfl_xor_sync(0xffffffffu, bv, o);
            int   oi = __shfl_xor_sync(0xffffffffu, bi, o);
            if (ov > bv || (ov == bv && oi < bi)) { bv = ov; bi = oi; }
        }
        if (lane == 0) { wv[warp] = bv; wi[warp] = bi; }
        __syncthreads();
        if (tid == 0) {
            float fv = wv[0]; int fi = wi[0];
#pragma unroll
            for (int i2 = 1; i2 < 8; i2++) {
                if (wv[i2] > fv || (wv[i2] == fv && wi[i2] < fi)) { fv = wv[i2]; fi = wi[i2]; }
            }
            long long id = (long long)fi * (long long)tm;
            if (mode == 1) out[1048576 + b] = (float)id;
            else ((long long*)(out + 1048576))[b] = id;
        }
    }
}

// ---------------------------------------------------------------------------
extern "C" void kernel_launch(void* const* d_in, const int* in_sizes, int n_in,
                              void* d_out, int out_size) {
    const float* ar     = (const float*)d_in[0];
    const int*   utm    = (const int*)d_in[1];
    const int*   tum    = (const int*)d_in[2];
    const float* ee     = (const float*)d_in[3];
    const float* W_func = (const float*)d_in[4];
    const float* b_func = (const float*)d_in[5];
    const float* W_conv = (const float*)d_in[6];
    const float* b_conv = (const float*)d_in[7];
    const float* W_fc1  = (const float*)d_in[8];
    const float* b_fc1  = (const float*)d_in[9];
    const float* W_fc2  = (const float*)d_in[10];
    const float* b_fc2  = (const float*)d_in[11];
    const float* lk     = (const float*)d_in[12];
    // d_in[13] = lstm_recurrent: unused (h0 = 0)
    const float* lb     = (const float*)d_in[14];

    kernelP0<<<128, 256>>>(W_fc1, W_fc2, b_fc1, b_fc2);

    int mode = 0;
    if (out_size >= 1048576 + 4096)      mode = 2;
    else if (out_size >= 1048576 + 2048) mode = 1;
    kernelBF<<<2048, 256>>>(ar, utm, tum, ee, W_func, b_func, W_conv, b_conv,
                            W_fc2, lk, lb, (float*)d_out, mode);
}